// round 1
// baseline (speedup 1.0000x reference)
#include <cuda_runtime.h>
#include <cuda_bf16.h>
#include <math.h>

// ---------------------------------------------------------------------------
// Shapes (fixed for this problem)
//   B=32, C=256, T=32, L=32, d=T*L=1024, K=8, G=4, D=32, H=128, n=2
// ---------------------------------------------------------------------------
#define Bn   32
#define Cn   256
#define Dn   1024      // d = T*L
#define Kn   8
#define Gn   4
#define DD   32        // slot feature dim D
#define Hn   128
#define OC   128       // G*D output channels

// ---------------- scratch (device globals; no runtime alloc) ----------------
__device__ float g_inp  [Bn * Cn * Dn];        // LN(tokens)          32 MB
__device__ float g_slots[Bn * Kn * Dn];
__device__ float g_sln  [Bn * Kn * Dn];
__device__ float g_q    [Bn * Kn * Dn];
__device__ float g_qw   [Bn * Kn * Dn];
__device__ float g_qbk  [Bn * Kn];
__device__ float g_dots [Bn * Kn * Cn];
__device__ float g_attn [Bn * Kn * Cn];
__device__ float g_aw   [Bn * Kn * Dn];
__device__ float g_upd  [Bn * Kn * Dn];
__device__ float g_gi   [Bn * Kn * 3 * Dn];
__device__ float g_gh   [Bn * Kn * 3 * Dn];
__device__ float g_hid  [Bn * Kn * Hn];
__device__ float g_W2p  [OC * 2 * Cn];         // (Wbr @ Wp) combined
__device__ float g_E    [Bn * OC * Cn];        // per-batch effective conv weight
__device__ float g_mean [OC];
__device__ float g_var  [OC];

// ---------------------------------------------------------------------------
__device__ __forceinline__ float warp_sum(float v) {
    #pragma unroll
    for (int o = 16; o; o >>= 1) v += __shfl_down_sync(0xFFFFFFFFu, v, o);
    return v;
}

// LayerNorm over rows of 1024 (eps = 1e-5, population variance)
__global__ void ln_rows_kernel(const float* __restrict__ x, const float* __restrict__ g,
                               const float* __restrict__ b, float* __restrict__ y)
{
    int row = blockIdx.x;
    const float* xr = x + (long long)row * Dn;
    int tid = threadIdx.x;
    float s = 0.f, ss = 0.f;
    for (int c = tid; c < Dn; c += 256) { float v = xr[c]; s += v; ss += v * v; }
    s = warp_sum(s); ss = warp_sum(ss);
    __shared__ float shs[8], shss[8];
    __shared__ float mean_s, rstd_s;
    int lane = tid & 31, w = tid >> 5;
    if (lane == 0) { shs[w] = s; shss[w] = ss; }
    __syncthreads();
    if (tid == 0) {
        float S = 0.f, SS = 0.f;
        #pragma unroll
        for (int i = 0; i < 8; i++) { S += shs[i]; SS += shss[i]; }
        float m = S * (1.f / Dn);
        float var = SS * (1.f / Dn) - m * m;
        mean_s = m;
        rstd_s = rsqrtf(var + 1e-5f);
    }
    __syncthreads();
    float m = mean_s, r = rstd_s;
    float* yr = y + (long long)row * Dn;
    for (int c = tid; c < Dn; c += 256) yr[c] = (xr[c] - m) * r * g[c] + b[c];
}

// slots = mu + exp(logsigma) * noise
__global__ void init_slots_kernel(const float* __restrict__ noise, const float* __restrict__ mu,
                                  const float* __restrict__ logsig, float* __restrict__ slots)
{
    int idx = blockIdx.x * 256 + threadIdx.x;       // < 262144
    int dch = idx & (Dn - 1);
    slots[idx] = mu[dch] + __expf(logsig[dch]) * noise[idx];
}

// -------- general SGEMM: C = act(A(MxK) * op(B) + bias [+ C]) --------------
// transB=1: B is NxK row-major (use B^T). transB=0: B is KxN row-major.
// act: 0=none, 1=relu, 2=gelu(exact). accum: C += result.
__global__ void gemm_kernel(const float* __restrict__ A, const float* __restrict__ B,
                            const float* __restrict__ bias, float* __restrict__ C,
                            int M, int N, int K,
                            long long sA, long long sB, long long sC,
                            int transB, int act, int accum)
{
    __shared__ float As[16][65];
    __shared__ float Bs[16][65];
    int bz = blockIdx.z;
    A += bz * sA; B += bz * sB; C += bz * sC;
    int m0 = blockIdx.y * 64, n0 = blockIdx.x * 64;
    int tid = threadIdx.x;
    int tx = tid & 15, ty = tid >> 4;
    float acc[4][4] = {};
    for (int k0 = 0; k0 < K; k0 += 16) {
        #pragma unroll
        for (int l = 0; l < 4; l++) {
            int idx = tid + l * 256;
            int mm = idx >> 4, kk = idx & 15;
            As[kk][mm] = A[(long long)(m0 + mm) * K + (k0 + kk)];
        }
        if (transB) {
            #pragma unroll
            for (int l = 0; l < 4; l++) {
                int idx = tid + l * 256;
                int nn = idx >> 4, kk = idx & 15;
                Bs[kk][nn] = B[(long long)(n0 + nn) * K + (k0 + kk)];
            }
        } else {
            #pragma unroll
            for (int l = 0; l < 4; l++) {
                int idx = tid + l * 256;
                int kk = idx >> 6, nn = idx & 63;
                Bs[kk][nn] = B[(long long)(k0 + kk) * N + (n0 + nn)];
            }
        }
        __syncthreads();
        #pragma unroll
        for (int kk = 0; kk < 16; kk++) {
            float a[4], bb[4];
            #pragma unroll
            for (int i = 0; i < 4; i++) a[i] = As[kk][ty + 16 * i];
            #pragma unroll
            for (int j = 0; j < 4; j++) bb[j] = Bs[kk][tx + 16 * j];
            #pragma unroll
            for (int i = 0; i < 4; i++)
                #pragma unroll
                for (int j = 0; j < 4; j++)
                    acc[i][j] += a[i] * bb[j];
        }
        __syncthreads();
    }
    #pragma unroll
    for (int i = 0; i < 4; i++) {
        int m = m0 + ty + 16 * i;
        if (m >= M) continue;
        #pragma unroll
        for (int j = 0; j < 4; j++) {
            int n = n0 + tx + 16 * j;
            if (n >= N) continue;
            float v = acc[i][j];
            if (bias) v += bias[n];
            long long off = (long long)m * N + n;
            if (accum) v += C[off];
            if (act == 1)      v = fmaxf(v, 0.f);
            else if (act == 2) v = 0.5f * v * (1.f + erff(v * 0.70710678118654752f));
            C[off] = v;
        }
    }
}

// qbk[row] = dot(q[row,:], bk)    (256 rows, one warp each)
__global__ void rowdot_kernel(const float* __restrict__ A, const float* __restrict__ v,
                              float* __restrict__ out)
{
    int row = blockIdx.x;
    float s = 0.f;
    for (int c = threadIdx.x; c < Dn; c += 32) s += A[(long long)row * Dn + c] * v[c];
    s = warp_sum(s);
    if (threadIdx.x == 0) out[row] = s;
}

// dots[b,i,j] = scale * (dot(qw[b,i,:], inp[b,j,:]) + qbk[b,i])
__global__ void dots_kernel(const float* __restrict__ qw, const float* __restrict__ inp,
                            const float* __restrict__ qbk, float* __restrict__ dots)
{
    int j = blockIdx.x, b = blockIdx.y;
    int tid = threadIdx.x;
    const float* ir = inp + ((long long)b * Cn + j) * Dn;
    const float* qb = qw + (long long)b * Kn * Dn;
    float acc[Kn] = {};
    for (int e = tid; e < Dn; e += 256) {
        float xv = ir[e];
        #pragma unroll
        for (int i = 0; i < Kn; i++) acc[i] += xv * qb[i * Dn + e];
    }
    __shared__ float sh[Kn][9];
    int lane = tid & 31, w = tid >> 5;
    #pragma unroll
    for (int i = 0; i < Kn; i++) {
        float s = warp_sum(acc[i]);
        if (lane == 0) sh[i][w] = s;
    }
    __syncthreads();
    if (tid < Kn) {
        float s = 0.f;
        #pragma unroll
        for (int w2 = 0; w2 < 8; w2++) s += sh[tid][w2];
        dots[((long long)b * Kn + tid) * Cn + j] = (s + qbk[b * Kn + tid]) * 0.03125f; // 1/sqrt(1024)
    }
}

// softmax over slot axis (K=8) + 1e-8
__global__ void softmax_slots_kernel(const float* __restrict__ dots, float* __restrict__ attn)
{
    int idx = blockIdx.x * 256 + threadIdx.x;       // < 8192
    int b = idx >> 8, j = idx & 255;
    const float* dp = dots + (long long)b * Kn * Cn + j;
    float v[Kn], mx = -1e30f;
    #pragma unroll
    for (int i = 0; i < Kn; i++) { v[i] = dp[i * Cn]; mx = fmaxf(mx, v[i]); }
    float s = 0.f;
    #pragma unroll
    for (int i = 0; i < Kn; i++) { v[i] = __expf(v[i] - mx); s += v[i]; }
    float inv = 1.f / s;
    float* ap = attn + (long long)b * Kn * Cn + j;
    #pragma unroll
    for (int i = 0; i < Kn; i++) ap[i * Cn] = v[i] * inv + 1e-8f;
}

// attn[row,:] /= (sum_j attn[row,j] + eps)
__global__ void rownorm_kernel(float* __restrict__ attn, float eps)
{
    int row = blockIdx.x;
    int tid = threadIdx.x;
    float v = attn[row * Cn + tid];
    float s = warp_sum(v);
    __shared__ float sh[8];
    __shared__ float total;
    int lane = tid & 31, w = tid >> 5;
    if (lane == 0) sh[w] = s;
    __syncthreads();
    if (tid == 0) {
        float S = 0.f;
        #pragma unroll
        for (int i = 0; i < 8; i++) S += sh[i];
        total = S + eps;
    }
    __syncthreads();
    attn[row * Cn + tid] = v / total;
}

// aw[b,i,:] = sum_j attn[b,i,j] * inp[b,j,:]
__global__ void aw_kernel(const float* __restrict__ attn, const float* __restrict__ inp,
                          float* __restrict__ aw)
{
    int row = blockIdx.x;               // b*8+i
    int b = row >> 3;
    int tid = threadIdx.x;
    __shared__ float a_s[Cn];
    a_s[tid] = attn[row * Cn + tid];
    __syncthreads();
    float a0 = 0.f, a1 = 0.f, a2 = 0.f, a3 = 0.f;
    const float* xb = inp + (long long)b * Cn * Dn;
    #pragma unroll 4
    for (int j = 0; j < Cn; j++) {
        float aj = a_s[j];
        const float* r = xb + (long long)j * Dn + tid;
        a0 += aj * r[0];
        a1 += aj * r[256];
        a2 += aj * r[512];
        a3 += aj * r[768];
    }
    float* o = aw + (long long)row * Dn + tid;
    o[0] = a0; o[256] = a1; o[512] = a2; o[768] = a3;
}

// GRU gate fusion: slots = (1-z)*tanh(ic + r*hc) + z*h
__global__ void gru_kernel(const float* __restrict__ gi, const float* __restrict__ gh,
                           float* __restrict__ slots)
{
    int idx = blockIdx.x * 256 + threadIdx.x;   // < 262144
    int r = idx >> 10, c = idx & (Dn - 1);
    long long base = (long long)r * 3 * Dn + c;
    float ir = gi[base], iz = gi[base + Dn], ic = gi[base + 2 * Dn];
    float hr = gh[base], hz = gh[base + Dn], hc = gh[base + 2 * Dn];
    float rg   = 1.f / (1.f + __expf(-(ir + hr)));
    float z    = 1.f / (1.f + __expf(-(iz + hz)));
    float cand = tanhf(ic + rg * hc);
    float h = slots[idx];
    slots[idx] = (1.f - z) * cand + z * h;
}

// W2p[o, j, c] = sum_{d'} Wbr[g, dd, j*32+d'] * Wp[d', c]   (o = g*32+dd)
__global__ void w2p_kernel(const float* __restrict__ Wbr, const float* __restrict__ Wp,
                           float* __restrict__ W2p)
{
    int o = blockIdx.x;
    int tid = threadIdx.x;
    __shared__ float wr[64];
    if (tid < 64) wr[tid] = Wbr[o * 64 + tid];
    __syncthreads();
    #pragma unroll
    for (int w = 0; w < 2; w++) {
        int idx = tid + w * 256;        // j*256 + c
        int j = idx >> 8, c = idx & 255;
        float s = 0.f;
        #pragma unroll
        for (int dp = 0; dp < 32; dp++) s += wr[j * 32 + dp] * Wp[dp * Cn + c];
        W2p[o * 512 + idx] = s;
    }
}

// E[b,o,c] = sum_{j=0,1} relu(gate[g*2+j]) * attn[b,g*2+j,c] * W2p[o,j,c]
__global__ void e_kernel(const float* __restrict__ attn, const float* __restrict__ W2p,
                         const float* __restrict__ gates, float* __restrict__ E)
{
    int idx = blockIdx.x * 256 + threadIdx.x;   // < 32*128*256
    int c = idx & 255, o = (idx >> 8) & 127, b = idx >> 15;
    int g = o >> 5;
    float s = 0.f;
    #pragma unroll
    for (int j = 0; j < 2; j++) {
        int k = g * 2 + j;
        float gt = fmaxf(gates[k], 0.f);
        s += gt * attn[((long long)b * Kn + k) * Cn + c] * W2p[o * 512 + j * 256 + c];
    }
    E[idx] = s;
}

// BatchNorm stats per channel o over (B, T*L): population mean/var
__global__ void bn_stats_kernel(const float* __restrict__ y, float* __restrict__ mean,
                                float* __restrict__ var)
{
    int o = blockIdx.x;
    int tid = threadIdx.x;
    float s = 0.f, ss = 0.f;
    for (int b = 0; b < Bn; b++) {
        const float* r = y + (long long)b * OC * Dn + (long long)o * Dn;
        for (int t = tid; t < Dn; t += 256) { float v = r[t]; s += v; ss += v * v; }
    }
    s = warp_sum(s); ss = warp_sum(ss);
    __shared__ float shs[8], shss[8];
    int lane = tid & 31, w = tid >> 5;
    if (lane == 0) { shs[w] = s; shss[w] = ss; }
    __syncthreads();
    if (tid == 0) {
        float S = 0.f, SS = 0.f;
        #pragma unroll
        for (int i = 0; i < 8; i++) { S += shs[i]; SS += shss[i]; }
        float m = S / (float)(Bn * Dn);
        mean[o] = m;
        var[o] = SS / (float)(Bn * Dn) - m * m;
    }
}

__global__ void bn_apply_kernel(float* __restrict__ y, const float* __restrict__ mean,
                                const float* __restrict__ var, const float* __restrict__ bg,
                                const float* __restrict__ bb)
{
    int idx = blockIdx.x * 256 + threadIdx.x;   // < 4194304
    int o = (idx >> 10) & 127;
    float v = y[idx];
    y[idx] = (v - mean[o]) * rsqrtf(var[o] + 1e-5f) * bg[o] + bb[o];
}

// ---------------------------------------------------------------------------
extern "C" void kernel_launch(void* const* d_in, const int* in_sizes, int n_in,
                              void* d_out, int out_size)
{
    const float* x       = (const float*)d_in[0];
    const float* noise   = (const float*)d_in[1];
    const float* mu      = (const float*)d_in[2];
    const float* logsig  = (const float*)d_in[3];
    const float* Wq      = (const float*)d_in[4];
    const float* bq      = (const float*)d_in[5];
    const float* Wk      = (const float*)d_in[6];
    const float* bk      = (const float*)d_in[7];
    const float* Wv      = (const float*)d_in[8];
    const float* bv      = (const float*)d_in[9];
    const float* W_ih    = (const float*)d_in[10];
    const float* b_ih    = (const float*)d_in[11];
    const float* W_hh    = (const float*)d_in[12];
    const float* b_hh    = (const float*)d_in[13];
    const float* W1      = (const float*)d_in[14];
    const float* b1      = (const float*)d_in[15];
    const float* W2      = (const float*)d_in[16];
    const float* b2      = (const float*)d_in[17];
    const float* ln_in_g = (const float*)d_in[18];
    const float* ln_in_b = (const float*)d_in[19];
    const float* ln_s_g  = (const float*)d_in[20];
    const float* ln_s_b  = (const float*)d_in[21];
    const float* ln_ff_g = (const float*)d_in[22];
    const float* ln_ff_b = (const float*)d_in[23];
    const float* Wp      = (const float*)d_in[24];
    const float* gates   = (const float*)d_in[25];
    const float* Wbr     = (const float*)d_in[26];
    const float* bn_g    = (const float*)d_in[27];
    const float* bn_b    = (const float*)d_in[28];
    float* out = (float*)d_out;

    float *inp, *slots, *sln, *q, *qw, *qbk, *dots, *attn, *aw, *upd, *gi, *gh,
          *hid, *W2p, *E, *mean, *var;
    cudaGetSymbolAddress((void**)&inp,   g_inp);
    cudaGetSymbolAddress((void**)&slots, g_slots);
    cudaGetSymbolAddress((void**)&sln,   g_sln);
    cudaGetSymbolAddress((void**)&q,     g_q);
    cudaGetSymbolAddress((void**)&qw,    g_qw);
    cudaGetSymbolAddress((void**)&qbk,   g_qbk);
    cudaGetSymbolAddress((void**)&dots,  g_dots);
    cudaGetSymbolAddress((void**)&attn,  g_attn);
    cudaGetSymbolAddress((void**)&aw,    g_aw);
    cudaGetSymbolAddress((void**)&upd,   g_upd);
    cudaGetSymbolAddress((void**)&gi,    g_gi);
    cudaGetSymbolAddress((void**)&gh,    g_gh);
    cudaGetSymbolAddress((void**)&hid,   g_hid);
    cudaGetSymbolAddress((void**)&W2p,   g_W2p);
    cudaGetSymbolAddress((void**)&E,     g_E);
    cudaGetSymbolAddress((void**)&mean,  g_mean);
    cudaGetSymbolAddress((void**)&var,   g_var);

    const int M = Bn * Kn;          // 256 slot rows

    // inp = LN(tokens)
    ln_rows_kernel<<<Bn * Cn, 256>>>(x, ln_in_g, ln_in_b, inp);
    // slots init
    init_slots_kernel<<<(Bn * Kn * Dn) / 256, 256>>>(noise, mu, logsig, slots);

    for (int it = 0; it < 3; it++) {
        // q = LN_s(slots) @ Wq^T + bq
        ln_rows_kernel<<<M, 256>>>(slots, ln_s_g, ln_s_b, sln);
        gemm_kernel<<<dim3(16, 4, 1), 256>>>(sln, Wq, bq, q, M, Dn, Dn, 0, 0, 0, 1, 0, 0);
        // qw = q @ Wk (NN);  qbk = q . bk
        gemm_kernel<<<dim3(16, 4, 1), 256>>>(q, Wk, nullptr, qw, M, Dn, Dn, 0, 0, 0, 0, 0, 0);
        rowdot_kernel<<<M, 32>>>(q, bk, qbk);
        // dots = scale * (qw . inp^T + qbk)
        dots_kernel<<<dim3(Cn, Bn, 1), 256>>>(qw, inp, qbk, dots);
        // attn = softmax over slots + 1e-8, then row-normalize
        softmax_slots_kernel<<<(Bn * Cn) / 256, 256>>>(dots, attn);
        rownorm_kernel<<<M, Cn>>>(attn, 0.f);
        // upd = (attn @ inp) @ Wv^T + bv
        aw_kernel<<<M, 256>>>(attn, inp, aw);
        gemm_kernel<<<dim3(16, 4, 1), 256>>>(aw, Wv, bv, upd, M, Dn, Dn, 0, 0, 0, 1, 0, 0);
        // GRU
        gemm_kernel<<<dim3(48, 4, 1), 256>>>(upd,   W_ih, b_ih, gi, M, 3 * Dn, Dn, 0, 0, 0, 1, 0, 0);
        gemm_kernel<<<dim3(48, 4, 1), 256>>>(slots, W_hh, b_hh, gh, M, 3 * Dn, Dn, 0, 0, 0, 1, 0, 0);
        gru_kernel<<<(M * Dn) / 256, 256>>>(gi, gh, slots);
        // MLP residual: slots += relu(LN_ff(slots) @ W1^T + b1) @ W2^T + b2
        ln_rows_kernel<<<M, 256>>>(slots, ln_ff_g, ln_ff_b, sln);
        gemm_kernel<<<dim3(2, 4, 1), 256>>>(sln, W1, b1, hid, M, Hn, Dn, 0, 0, 0, 1, 1, 0);
        gemm_kernel<<<dim3(16, 4, 1), 256>>>(hid, W2, b2, slots, M, Dn, Hn, 0, 0, 0, 1, 0, 1);
    }

    // final renorm with +1e-9
    rownorm_kernel<<<M, Cn>>>(attn, 1e-9f);

    // fused router + branch: effective weight E, then batched GEMM vs x + GELU
    w2p_kernel<<<OC, 256>>>(Wbr, Wp, W2p);
    e_kernel<<<(Bn * OC * Cn) / 256, 256>>>(attn, W2p, gates, E);
    gemm_kernel<<<dim3(16, 2, Bn), 256>>>(E, x, nullptr, out,
                                          OC, Dn, Cn,
                                          (long long)OC * Cn, (long long)Cn * Dn,
                                          (long long)OC * Dn,
                                          0, 2 /*gelu*/, 0);

    // BatchNorm (batch stats) in place on out
    bn_stats_kernel<<<OC, 256>>>(out, mean, var);
    bn_apply_kernel<<<(Bn * OC * Dn) / 256, 256>>>(out, mean, var, bn_g, bn_b);
}

// round 2
// speedup vs baseline: 1.9880x; 1.9880x over previous
#include <cuda_runtime.h>
#include <cuda_bf16.h>
#include <math.h>

// ---------------------------------------------------------------------------
// Shapes (fixed): B=32, C=256, T=32, L=32, d=1024, K=8, G=4, D=32, H=128
// ---------------------------------------------------------------------------
#define Bn   32
#define Cn   256
#define Dn   1024
#define Kn   8
#define Gn   4
#define Hn   128
#define OC   128

// ---------------- scratch (device globals; no runtime alloc) ----------------
__device__ float g_inp  [Bn * Cn * Dn];
__device__ float g_slots[Bn * Kn * Dn];
__device__ float g_sln  [Bn * Kn * Dn];
__device__ float g_q    [Bn * Kn * Dn];
__device__ float g_qw   [Bn * Kn * Dn];
__device__ float g_qbk  [Bn * Kn];
__device__ float g_dots [Bn * Kn * Cn];
__device__ float g_attn [Bn * Kn * Cn];
__device__ float g_aw   [Bn * Kn * Dn];
__device__ float g_upd  [Bn * Kn * Dn];
__device__ float g_gi   [Bn * Kn * 3 * Dn];
__device__ float g_gh   [Bn * Kn * 3 * Dn];
__device__ float g_hid  [Bn * Kn * Hn];
__device__ float g_W2p  [OC * 2 * Cn];
__device__ float g_E    [Bn * OC * Cn];
__device__ float g_mean [OC];
__device__ float g_var  [OC];
__device__ float g_part [8 * 256 * 1024];      // split-K partials workspace (8MB)

// ---------------------------------------------------------------------------
__device__ __forceinline__ float warp_sum(float v) {
    #pragma unroll
    for (int o = 16; o; o >>= 1) v += __shfl_down_sync(0xFFFFFFFFu, v, o);
    return v;
}

// LayerNorm over rows of 1024
__global__ void ln_rows_kernel(const float* __restrict__ x, const float* __restrict__ g,
                               const float* __restrict__ b, float* __restrict__ y)
{
    int row = blockIdx.x;
    const float* xr = x + (long long)row * Dn;
    int tid = threadIdx.x;
    float s = 0.f, ss = 0.f;
    for (int c = tid; c < Dn; c += 256) { float v = xr[c]; s += v; ss += v * v; }
    s = warp_sum(s); ss = warp_sum(ss);
    __shared__ float shs[8], shss[8];
    __shared__ float mean_s, rstd_s;
    int lane = tid & 31, w = tid >> 5;
    if (lane == 0) { shs[w] = s; shss[w] = ss; }
    __syncthreads();
    if (tid == 0) {
        float S = 0.f, SS = 0.f;
        #pragma unroll
        for (int i = 0; i < 8; i++) { S += shs[i]; SS += shss[i]; }
        float m = S * (1.f / Dn);
        float var = SS * (1.f / Dn) - m * m;
        mean_s = m;
        rstd_s = rsqrtf(var + 1e-5f);
    }
    __syncthreads();
    float m = mean_s, r = rstd_s;
    float* yr = y + (long long)row * Dn;
    for (int c = tid; c < Dn; c += 256) yr[c] = (xr[c] - m) * r * g[c] + b[c];
}

__global__ void init_slots_kernel(const float* __restrict__ noise, const float* __restrict__ mu,
                                  const float* __restrict__ logsig, float* __restrict__ slots)
{
    int idx = blockIdx.x * 256 + threadIdx.x;
    int dch = idx & (Dn - 1);
    slots[idx] = mu[dch] + __expf(logsig[dch]) * noise[idx];
}

// ---------------------------------------------------------------------------
// Double-buffered split-K SGEMM. 64x64 tile, BK=16, 4x4 microtile, 256 thr.
// All of M, N assumed multiples of 64; K multiple of 16*KS.
// KS==1: epilogue (bias/accum/act) applied directly to C (per-batch via bz or
//        dual-mode via A2/B2 pointer set).  KS>1: raw partials to C=workspace.
// act: 0 none, 1 relu, 2 gelu(exact)
// ---------------------------------------------------------------------------
__global__ void __launch_bounds__(256, 2)
gemm_db(const float* __restrict__ A, const float* __restrict__ B,
        const float* __restrict__ bias, float* __restrict__ C,
        int M, int N, int K, int KS, int mblocks,
        long long sA, long long sB, long long sC,
        int transB, int act, int accum,
        const float* __restrict__ A2, const float* __restrict__ B2,
        const float* __restrict__ bias2, float* __restrict__ C2)
{
    __shared__ __align__(16) float As[2][16][66];
    __shared__ __align__(16) float Bs[2][16][68];
    int bz = blockIdx.z;
    const float* bp = bias;
    if (A2) {
        if (bz) { A = A2; B = B2; bp = bias2; C = C2; }
    } else if (bz) {
        A += bz * sA; B += bz * sB; C += bz * sC;
    }
    int mb = blockIdx.y % mblocks;
    int ks = blockIdx.y / mblocks;
    int m0 = mb * 64, n0 = blockIdx.x * 64;
    int Kc = K / KS;
    int kbeg = ks * Kc;
    int tid = threadIdx.x, tx = tid & 15, ty = tid >> 4;

    int ar = tid >> 2, ak = (tid & 3) * 4;          // transposed-store indices
    const float* Ap = A + (long long)(m0 + ar) * K + ak + kbeg;
    const float* Bp;
    if (transB) Bp = B + (long long)(n0 + ar) * K + ak + kbeg;
    else        Bp = B + (long long)(kbeg + (tid >> 4)) * N + n0 + (tid & 15) * 4;

    int nk = Kc >> 4;

    // prologue: tile 0 -> buffer 0
    {
        float4 aq = *(const float4*)Ap;
        As[0][ak + 0][ar] = aq.x; As[0][ak + 1][ar] = aq.y;
        As[0][ak + 2][ar] = aq.z; As[0][ak + 3][ar] = aq.w;
        if (transB) {
            float4 bq = *(const float4*)Bp;
            Bs[0][ak + 0][ar] = bq.x; Bs[0][ak + 1][ar] = bq.y;
            Bs[0][ak + 2][ar] = bq.z; Bs[0][ak + 3][ar] = bq.w;
        } else {
            float4 bq = *(const float4*)Bp;
            *(float4*)&Bs[0][tid >> 4][(tid & 15) * 4] = bq;
        }
    }
    __syncthreads();

    float acc[4][4] = {};
    int cur = 0;
    for (int t = 0; t < nk; t++) {
        float4 aqn, bqn;
        bool more = (t + 1 < nk);
        if (more) {
            aqn = *(const float4*)(Ap + (t + 1) * 16);
            if (transB) bqn = *(const float4*)(Bp + (t + 1) * 16);
            else        bqn = *(const float4*)(Bp + (long long)(t + 1) * 16 * N);
        }
        #pragma unroll
        for (int kk = 0; kk < 16; kk++) {
            float a[4], bb[4];
            #pragma unroll
            for (int i = 0; i < 4; i++) a[i] = As[cur][kk][ty + 16 * i];
            #pragma unroll
            for (int j = 0; j < 4; j++) bb[j] = Bs[cur][kk][tx + 16 * j];
            #pragma unroll
            for (int i = 0; i < 4; i++)
                #pragma unroll
                for (int j = 0; j < 4; j++)
                    acc[i][j] += a[i] * bb[j];
        }
        if (more) {
            int nb = cur ^ 1;
            As[nb][ak + 0][ar] = aqn.x; As[nb][ak + 1][ar] = aqn.y;
            As[nb][ak + 2][ar] = aqn.z; As[nb][ak + 3][ar] = aqn.w;
            if (transB) {
                Bs[nb][ak + 0][ar] = bqn.x; Bs[nb][ak + 1][ar] = bqn.y;
                Bs[nb][ak + 2][ar] = bqn.z; Bs[nb][ak + 3][ar] = bqn.w;
            } else {
                *(float4*)&Bs[nb][tid >> 4][(tid & 15) * 4] = bqn;
            }
        }
        __syncthreads();
        cur ^= 1;
    }

    if (KS == 1) {
        #pragma unroll
        for (int i = 0; i < 4; i++) {
            int m = m0 + ty + 16 * i;
            float* Cr = C + (long long)m * N + n0;
            #pragma unroll
            for (int j = 0; j < 4; j++) {
                int n = tx + 16 * j;
                float v = acc[i][j];
                if (bp) v += bp[n0 + n];
                if (accum) v += Cr[n];
                if (act == 1)      v = fmaxf(v, 0.f);
                else if (act == 2) v = 0.5f * v * (1.f + erff(v * 0.70710678118654752f));
                Cr[n] = v;
            }
        }
    } else {
        float* Pr = C + (long long)ks * M * N;
        #pragma unroll
        for (int i = 0; i < 4; i++) {
            int m = m0 + ty + 16 * i;
            #pragma unroll
            for (int j = 0; j < 4; j++)
                Pr[(long long)m * N + n0 + tx + 16 * j] = acc[i][j];
        }
    }
}

// combine split-K partials: C = act(sum_ks P + bias [+ C])
__global__ void combine_kernel(const float* __restrict__ P, const float* __restrict__ bias,
                               float* __restrict__ C, int MN, int N, int KS,
                               int act, int accum)
{
    int idx = blockIdx.x * 256 + threadIdx.x;
    float s = 0.f;
    for (int ks = 0; ks < KS; ks++) s += P[(long long)ks * MN + idx];
    if (bias) s += bias[idx % N];
    if (accum) s += C[idx];
    if (act == 1) s = fmaxf(s, 0.f);
    C[idx] = s;
}

// qbk[row] = dot(q[row,:], bk)
__global__ void rowdot_kernel(const float* __restrict__ A, const float* __restrict__ v,
                              float* __restrict__ out)
{
    int row = blockIdx.x;
    float s = 0.f;
    for (int c = threadIdx.x; c < Dn; c += 32) s += A[(long long)row * Dn + c] * v[c];
    s = warp_sum(s);
    if (threadIdx.x == 0) out[row] = s;
}

// dots[b,i,j] = scale * (dot(qw[b,i,:], inp[b,j,:]) + qbk[b,i])
__global__ void dots_kernel(const float* __restrict__ qw, const float* __restrict__ inp,
                            const float* __restrict__ qbk, float* __restrict__ dots)
{
    int j = blockIdx.x, b = blockIdx.y;
    int tid = threadIdx.x;
    const float* ir = inp + ((long long)b * Cn + j) * Dn;
    const float* qb = qw + (long long)b * Kn * Dn;
    float acc[Kn] = {};
    for (int e = tid; e < Dn; e += 256) {
        float xv = ir[e];
        #pragma unroll
        for (int i = 0; i < Kn; i++) acc[i] += xv * qb[i * Dn + e];
    }
    __shared__ float sh[Kn][9];
    int lane = tid & 31, w = tid >> 5;
    #pragma unroll
    for (int i = 0; i < Kn; i++) {
        float s = warp_sum(acc[i]);
        if (lane == 0) sh[i][w] = s;
    }
    __syncthreads();
    if (tid < Kn) {
        float s = 0.f;
        #pragma unroll
        for (int w2 = 0; w2 < 8; w2++) s += sh[tid][w2];
        dots[((long long)b * Kn + tid) * Cn + j] = (s + qbk[b * Kn + tid]) * 0.03125f;
    }
}

// softmax over slot axis (K=8) + 1e-8
__global__ void softmax_slots_kernel(const float* __restrict__ dots, float* __restrict__ attn)
{
    int idx = blockIdx.x * 256 + threadIdx.x;
    int b = idx >> 8, j = idx & 255;
    const float* dp = dots + (long long)b * Kn * Cn + j;
    float v[Kn], mx = -1e30f;
    #pragma unroll
    for (int i = 0; i < Kn; i++) { v[i] = dp[i * Cn]; mx = fmaxf(mx, v[i]); }
    float s = 0.f;
    #pragma unroll
    for (int i = 0; i < Kn; i++) { v[i] = __expf(v[i] - mx); s += v[i]; }
    float inv = 1.f / s;
    float* ap = attn + (long long)b * Kn * Cn + j;
    #pragma unroll
    for (int i = 0; i < Kn; i++) ap[i * Cn] = v[i] * inv + 1e-8f;
}

__global__ void rownorm_kernel(float* __restrict__ attn, float eps)
{
    int row = blockIdx.x;
    int tid = threadIdx.x;
    float v = attn[row * Cn + tid];
    float s = warp_sum(v);
    __shared__ float sh[8];
    __shared__ float total;
    int lane = tid & 31, w = tid >> 5;
    if (lane == 0) sh[w] = s;
    __syncthreads();
    if (tid == 0) {
        float S = 0.f;
        #pragma unroll
        for (int i = 0; i < 8; i++) S += sh[i];
        total = S + eps;
    }
    __syncthreads();
    attn[row * Cn + tid] = v / total;
}

// aw[b,i,:] = sum_j attn[b,i,j] * inp[b,j,:]
__global__ void aw_kernel(const float* __restrict__ attn, const float* __restrict__ inp,
                          float* __restrict__ aw)
{
    int row = blockIdx.x;
    int b = row >> 3;
    int tid = threadIdx.x;
    __shared__ float a_s[Cn];
    a_s[tid] = attn[row * Cn + tid];
    __syncthreads();
    float a0 = 0.f, a1 = 0.f, a2 = 0.f, a3 = 0.f;
    const float* xb = inp + (long long)b * Cn * Dn;
    #pragma unroll 4
    for (int j = 0; j < Cn; j++) {
        float aj = a_s[j];
        const float* r = xb + (long long)j * Dn + tid;
        a0 += aj * r[0];
        a1 += aj * r[256];
        a2 += aj * r[512];
        a3 += aj * r[768];
    }
    float* o = aw + (long long)row * Dn + tid;
    o[0] = a0; o[256] = a1; o[512] = a2; o[768] = a3;
}

// GRU gate fusion
__global__ void gru_kernel(const float* __restrict__ gi, const float* __restrict__ gh,
                           float* __restrict__ slots)
{
    int idx = blockIdx.x * 256 + threadIdx.x;
    int r = idx >> 10, c = idx & (Dn - 1);
    long long base = (long long)r * 3 * Dn + c;
    float ir = gi[base], iz = gi[base + Dn], ic = gi[base + 2 * Dn];
    float hr = gh[base], hz = gh[base + Dn], hc = gh[base + 2 * Dn];
    float rg   = 1.f / (1.f + __expf(-(ir + hr)));
    float z    = 1.f / (1.f + __expf(-(iz + hz)));
    float cand = tanhf(ic + rg * hc);
    float h = slots[idx];
    slots[idx] = (1.f - z) * cand + z * h;
}

// W2p[o, j, c] = sum_{d'} Wbr[g, dd, j*32+d'] * Wp[d', c]
__global__ void w2p_kernel(const float* __restrict__ Wbr, const float* __restrict__ Wp,
                           float* __restrict__ W2p)
{
    int o = blockIdx.x;
    int tid = threadIdx.x;
    __shared__ float wr[64];
    if (tid < 64) wr[tid] = Wbr[o * 64 + tid];
    __syncthreads();
    #pragma unroll
    for (int w = 0; w < 2; w++) {
        int idx = tid + w * 256;
        int j = idx >> 8, c = idx & 255;
        float s = 0.f;
        #pragma unroll
        for (int dp = 0; dp < 32; dp++) s += wr[j * 32 + dp] * Wp[dp * Cn + c];
        W2p[o * 512 + idx] = s;
    }
}

// E[b,o,c] = sum_j relu(gate[g*2+j]) * attn[b,g*2+j,c] * W2p[o,j,c]
__global__ void e_kernel(const float* __restrict__ attn, const float* __restrict__ W2p,
                         const float* __restrict__ gates, float* __restrict__ E)
{
    int idx = blockIdx.x * 256 + threadIdx.x;
    int c = idx & 255, o = (idx >> 8) & 127, b = idx >> 15;
    int g = o >> 5;
    float s = 0.f;
    #pragma unroll
    for (int j = 0; j < 2; j++) {
        int k = g * 2 + j;
        float gt = fmaxf(gates[k], 0.f);
        s += gt * attn[((long long)b * Kn + k) * Cn + c] * W2p[o * 512 + j * 256 + c];
    }
    E[idx] = s;
}

__global__ void bn_stats_kernel(const float* __restrict__ y, float* __restrict__ mean,
                                float* __restrict__ var)
{
    int o = blockIdx.x;
    int tid = threadIdx.x;
    float s = 0.f, ss = 0.f;
    for (int b = 0; b < Bn; b++) {
        const float* r = y + (long long)b * OC * Dn + (long long)o * Dn;
        for (int t = tid; t < Dn; t += 256) { float v = r[t]; s += v; ss += v * v; }
    }
    s = warp_sum(s); ss = warp_sum(ss);
    __shared__ float shs[8], shss[8];
    int lane = tid & 31, w = tid >> 5;
    if (lane == 0) { shs[w] = s; shss[w] = ss; }
    __syncthreads();
    if (tid == 0) {
        float S = 0.f, SS = 0.f;
        #pragma unroll
        for (int i = 0; i < 8; i++) { S += shs[i]; SS += shss[i]; }
        float m = S / (float)(Bn * Dn);
        mean[o] = m;
        var[o] = SS / (float)(Bn * Dn) - m * m;
    }
}

__global__ void bn_apply_kernel(float* __restrict__ y, const float* __restrict__ mean,
                                const float* __restrict__ var, const float* __restrict__ bg,
                                const float* __restrict__ bb)
{
    int idx = blockIdx.x * 256 + threadIdx.x;
    int o = (idx >> 10) & 127;
    float v = y[idx];
    y[idx] = (v - mean[o]) * rsqrtf(var[o] + 1e-5f) * bg[o] + bb[o];
}

// ---------------------------------------------------------------------------
extern "C" void kernel_launch(void* const* d_in, const int* in_sizes, int n_in,
                              void* d_out, int out_size)
{
    const float* x       = (const float*)d_in[0];
    const float* noise   = (const float*)d_in[1];
    const float* mu      = (const float*)d_in[2];
    const float* logsig  = (const float*)d_in[3];
    const float* Wq      = (const float*)d_in[4];
    const float* bq      = (const float*)d_in[5];
    const float* Wk      = (const float*)d_in[6];
    const float* bk      = (const float*)d_in[7];
    const float* Wv      = (const float*)d_in[8];
    const float* bv      = (const float*)d_in[9];
    const float* W_ih    = (const float*)d_in[10];
    const float* b_ih    = (const float*)d_in[11];
    const float* W_hh    = (const float*)d_in[12];
    const float* b_hh    = (const float*)d_in[13];
    const float* W1      = (const float*)d_in[14];
    const float* b1      = (const float*)d_in[15];
    const float* W2      = (const float*)d_in[16];
    const float* b2      = (const float*)d_in[17];
    const float* ln_in_g = (const float*)d_in[18];
    const float* ln_in_b = (const float*)d_in[19];
    const float* ln_s_g  = (const float*)d_in[20];
    const float* ln_s_b  = (const float*)d_in[21];
    const float* ln_ff_g = (const float*)d_in[22];
    const float* ln_ff_b = (const float*)d_in[23];
    const float* Wp      = (const float*)d_in[24];
    const float* gates   = (const float*)d_in[25];
    const float* Wbr     = (const float*)d_in[26];
    const float* bn_g    = (const float*)d_in[27];
    const float* bn_b    = (const float*)d_in[28];
    float* out = (float*)d_out;

    float *inp, *slots, *sln, *q, *qw, *qbk, *dots, *attn, *aw, *upd, *gi, *gh,
          *hid, *W2p, *E, *mean, *var, *part;
    cudaGetSymbolAddress((void**)&inp,   g_inp);
    cudaGetSymbolAddress((void**)&slots, g_slots);
    cudaGetSymbolAddress((void**)&sln,   g_sln);
    cudaGetSymbolAddress((void**)&q,     g_q);
    cudaGetSymbolAddress((void**)&qw,    g_qw);
    cudaGetSymbolAddress((void**)&qbk,   g_qbk);
    cudaGetSymbolAddress((void**)&dots,  g_dots);
    cudaGetSymbolAddress((void**)&attn,  g_attn);
    cudaGetSymbolAddress((void**)&aw,    g_aw);
    cudaGetSymbolAddress((void**)&upd,   g_upd);
    cudaGetSymbolAddress((void**)&gi,    g_gi);
    cudaGetSymbolAddress((void**)&gh,    g_gh);
    cudaGetSymbolAddress((void**)&hid,   g_hid);
    cudaGetSymbolAddress((void**)&W2p,   g_W2p);
    cudaGetSymbolAddress((void**)&E,     g_E);
    cudaGetSymbolAddress((void**)&mean,  g_mean);
    cudaGetSymbolAddress((void**)&var,   g_var);
    cudaGetSymbolAddress((void**)&part,  g_part);

    const int M = Bn * Kn;          // 256 slot rows

    ln_rows_kernel<<<Bn * Cn, 256>>>(x, ln_in_g, ln_in_b, inp);
    init_slots_kernel<<<(Bn * Kn * Dn) / 256, 256>>>(noise, mu, logsig, slots);

    for (int it = 0; it < 3; it++) {
        // q = LN_s(slots) @ Wq^T + bq   (KS=4)
        ln_rows_kernel<<<M, 256>>>(slots, ln_s_g, ln_s_b, sln);
        gemm_db<<<dim3(16, 16), 256>>>(sln, Wq, nullptr, part, M, Dn, Dn, 4, 4,
                                       0, 0, 0, 1, 0, 0, nullptr, nullptr, nullptr, nullptr);
        combine_kernel<<<(M * Dn) / 256, 256>>>(part, bq, q, M * Dn, Dn, 4, 0, 0);
        // qw = q @ Wk   (KS=4)
        gemm_db<<<dim3(16, 16), 256>>>(q, Wk, nullptr, part, M, Dn, Dn, 4, 4,
                                       0, 0, 0, 0, 0, 0, nullptr, nullptr, nullptr, nullptr);
        combine_kernel<<<(M * Dn) / 256, 256>>>(part, nullptr, qw, M * Dn, Dn, 4, 0, 0);
        rowdot_kernel<<<M, 32>>>(q, bk, qbk);
        // dots, softmax, normalize
        dots_kernel<<<dim3(Cn, Bn), 256>>>(qw, inp, qbk, dots);
        softmax_slots_kernel<<<(Bn * Cn) / 256, 256>>>(dots, attn);
        rownorm_kernel<<<M, Cn>>>(attn, 0.f);
        // upd = (attn @ inp) @ Wv^T + bv   (KS=4)
        aw_kernel<<<M, 256>>>(attn, inp, aw);
        gemm_db<<<dim3(16, 16), 256>>>(aw, Wv, nullptr, part, M, Dn, Dn, 4, 4,
                                       0, 0, 0, 1, 0, 0, nullptr, nullptr, nullptr, nullptr);
        combine_kernel<<<(M * Dn) / 256, 256>>>(part, bv, upd, M * Dn, Dn, 4, 0, 0);
        // GRU: gi and gh in one dual launch (KS=1, bias in epilogue)
        gemm_db<<<dim3(48, 4, 2), 256>>>(upd, W_ih, b_ih, gi, M, 3 * Dn, Dn, 1, 4,
                                         0, 0, 0, 1, 0, 0, slots, W_hh, b_hh, gh);
        gru_kernel<<<(M * Dn) / 256, 256>>>(gi, gh, slots);
        // MLP residual
        ln_rows_kernel<<<M, 256>>>(slots, ln_ff_g, ln_ff_b, sln);
        gemm_db<<<dim3(2, 32), 256>>>(sln, W1, nullptr, part, M, Hn, Dn, 8, 4,
                                      0, 0, 0, 1, 0, 0, nullptr, nullptr, nullptr, nullptr);
        combine_kernel<<<(M * Hn) / 256, 256>>>(part, b1, hid, M * Hn, Hn, 8, 1, 0);
        gemm_db<<<dim3(16, 8), 256>>>(hid, W2, nullptr, part, M, Dn, Hn, 2, 4,
                                      0, 0, 0, 1, 0, 0, nullptr, nullptr, nullptr, nullptr);
        combine_kernel<<<(M * Dn) / 256, 256>>>(part, b2, slots, M * Dn, Dn, 2, 0, 1);
    }

    rownorm_kernel<<<M, Cn>>>(attn, 1e-9f);

    // fused router + branch
    w2p_kernel<<<OC, 256>>>(Wbr, Wp, W2p);
    e_kernel<<<(Bn * OC * Cn) / 256, 256>>>(attn, W2p, gates, E);
    gemm_db<<<dim3(16, 2, Bn), 256>>>(E, x, nullptr, out, OC, Dn, Cn, 1, 2,
                                      (long long)OC * Cn, (long long)Cn * Dn,
                                      (long long)OC * Dn, 0, 2, 0,
                                      nullptr, nullptr, nullptr, nullptr);

    bn_stats_kernel<<<OC, 256>>>(out, mean, var);
    bn_apply_kernel<<<(Bn * OC * Dn) / 256, 256>>>(out, mean, var, bn_g, bn_b);
}